// round 15
// baseline (speedup 1.0000x reference)
#include <cuda_runtime.h>
#include <math.h>
#include <float.h>

#define NN 8192
#define DD 64
#define EE 524288

// ---------------- static device scratch -------------------------------------
__device__ __align__(16) float g_AH [NN*DD];
__device__ __align__(16) float g_ft0[NN*DD];
__device__ __align__(16) float g_ft1[NN*DD];
__device__ __align__(16) float g_ft2[NN*DD];
__device__ __align__(16) float g_w0 [EE];
__device__ __align__(16) int   g_sent[EE];     // dst | m1<<14 | m2<<15 (src-CSR)
__device__ __align__(16) int   g_dent[EE];     // src | m1<<14 | m2<<15 (dst-CSR)
__device__ __align__(16) unsigned char g_bits[EE];
__device__ __align__(16) unsigned g_mult[1<<24];  // 64MB byte-counters, key=(s<<13)|d
__device__ __align__(16) int   g_hists[NN];
__device__ __align__(16) int   g_histd[NN];
__device__ __align__(16) int   g_offs[NN+8];
__device__ __align__(16) int   g_offd[NN+8];
__device__ __align__(16) int   g_curs[NN];
__device__ __align__(16) int   g_curd[NN];
__device__ int   g_nm1[NN], g_nm2[NN];
__device__ float g_pool[3*DD];
__device__ __align__(16) float g_M [3][DD*DD]; // M_k = Ww.T @ fc_k
__device__ __align__(16) float g_b [3][DD];    // b_k = Wb @ fc_k

// ---------------- hist + A1/A2 probes + multiplicity count (fused) -----------
__global__ void k_histbits(const int* __restrict__ src, const int* __restrict__ dst,
                           const float* __restrict__ A1, const float* __restrict__ A2){
    int e4 = blockIdx.x*blockDim.x + threadIdx.x;
    if (e4 >= EE/4) return;
    int4 s = ((const int4*)src)[e4];
    int4 d = ((const int4*)dst)[e4];
    float a1x = __ldcs(&A1[(size_t)s.x*NN + d.x]);
    float a1y = __ldcs(&A1[(size_t)s.y*NN + d.y]);
    float a1z = __ldcs(&A1[(size_t)s.z*NN + d.z]);
    float a1w = __ldcs(&A1[(size_t)s.w*NN + d.w]);
    float a2x = __ldcs(&A2[(size_t)s.x*NN + d.x]);
    float a2y = __ldcs(&A2[(size_t)s.y*NN + d.y]);
    float a2z = __ldcs(&A2[(size_t)s.z*NN + d.z]);
    float a2w = __ldcs(&A2[(size_t)s.w*NN + d.w]);
    int kx = (s.x<<13)|d.x, ky = (s.y<<13)|d.y, kz = (s.z<<13)|d.z, kw = (s.w<<13)|d.w;
    atomicAdd(&g_mult[kx>>2], 1u<<((kx&3)*8));
    atomicAdd(&g_mult[ky>>2], 1u<<((ky&3)*8));
    atomicAdd(&g_mult[kz>>2], 1u<<((kz&3)*8));
    atomicAdd(&g_mult[kw>>2], 1u<<((kw&3)*8));
    atomicAdd(&g_hists[s.x], 1); atomicAdd(&g_hists[s.y], 1);
    atomicAdd(&g_hists[s.z], 1); atomicAdd(&g_hists[s.w], 1);
    atomicAdd(&g_histd[d.x], 1); atomicAdd(&g_histd[d.y], 1);
    atomicAdd(&g_histd[d.z], 1); atomicAdd(&g_histd[d.w], 1);
    uchar4 b;
    b.x = (unsigned char)(((a1x > 0.f) ? 1 : 0) | ((a2x > 0.f) ? 2 : 0));
    b.y = (unsigned char)(((a1y > 0.f) ? 1 : 0) | ((a2y > 0.f) ? 2 : 0));
    b.z = (unsigned char)(((a1z > 0.f) ? 1 : 0) | ((a2z > 0.f) ? 2 : 0));
    b.w = (unsigned char)(((a1w > 0.f) ? 1 : 0) | ((a2w > 0.f) ? 2 : 0));
    ((uchar4*)g_bits)[e4] = b;
}

// ---------------- scan (blocks 0,1) + M_k/b_k precompute (blocks 2..4) --------
__global__ void k_scan(const float* __restrict__ Ww, const float* __restrict__ Wb,
                       const float* __restrict__ fc0, const float* __restrict__ fc1,
                       const float* __restrict__ fc2){
    int t = threadIdx.x;         // 1024
    if (blockIdx.x >= 2){
        int q = blockIdx.x - 2;
        const float* fc = (q==0) ? fc0 : (q==1 ? fc1 : fc2);
        __shared__ float sWw[DD*DD], sfc[DD*DD];
        for (int x=t; x<DD*DD; x+=1024){ sWw[x] = Ww[x]; sfc[x] = fc[x]; }
        __syncthreads();
        for (int x=t; x<DD*DD; x+=1024){
            int k = x >> 6, j = x & 63;
            float acc = 0.f, acc2 = 0.f;
            #pragma unroll 8
            for (int r=0;r<DD;r+=2){
                acc  += sWw[r*DD+k]     * sfc[r*DD+j];
                acc2 += sWw[(r+1)*DD+k] * sfc[(r+1)*DD+j];
            }
            g_M[q][x] = acc + acc2;
        }
        if (t < DD){
            float acc = 0.f;
            for (int r=0;r<DD;r++) acc += Wb[r] * sfc[r*DD+t];
            g_b[q][t] = acc;
        }
        return;
    }
    int* hist = blockIdx.x ? g_histd : g_hists;
    int* off  = blockIdx.x ? g_offd  : g_offs;
    int* cur  = blockIdx.x ? g_curd  : g_curs;
    __shared__ int wsum[32];
    int lane = t & 31, wid = t >> 5;
    int4 a = ((const int4*)hist)[2*t];
    int4 b = ((const int4*)hist)[2*t+1];
    int l0=a.x, l1=l0+a.y, l2=l1+a.z, l3=l2+a.w;
    int l4=l3+b.x, l5=l4+b.y, l6=l5+b.z, l7=l6+b.w;
    int4 z4 = make_int4(0,0,0,0);
    ((int4*)hist)[2*t]   = z4;
    ((int4*)hist)[2*t+1] = z4;
    int tot = l7;
    int pre = tot;
    #pragma unroll
    for (int o=1;o<32;o<<=1){ int v=__shfl_up_sync(0xffffffffu, pre, o); if (lane>=o) pre += v; }
    int wex = pre - tot;
    if (lane == 31) wsum[wid] = pre;
    __syncthreads();
    if (wid == 0){
        int v = wsum[lane];
        int p = v;
        #pragma unroll
        for (int o=1;o<32;o<<=1){ int u=__shfl_up_sync(0xffffffffu, p, o); if (lane>=o) p += u; }
        wsum[lane] = p - v;
    }
    __syncthreads();
    int base = wsum[wid] + wex;
    int4 o0 = make_int4(base,    base+l0, base+l1, base+l2);
    int4 o1 = make_int4(base+l3, base+l4, base+l5, base+l6);
    ((int4*)off)[2*t]   = o0;  ((int4*)off)[2*t+1] = o1;
    ((int4*)cur)[2*t]   = o0;  ((int4*)cur)[2*t+1] = o1;
    if (t == 1023) off[NN] = base + l7;
}

// ---------------- scatter: CSR build + w0 = 1/mult ----------------------------
__global__ void k_scatter(const int* __restrict__ src, const int* __restrict__ dst){
    int e2 = blockIdx.x*blockDim.x + threadIdx.x;
    if (e2 >= EE/2) return;
    int2 s = ((const int2*)src)[e2];
    int2 d = ((const int2*)dst)[e2];
    uchar2 b = ((const uchar2*)g_bits)[e2];
    int kx = (s.x<<13)|d.x, ky = (s.y<<13)|d.y;
    unsigned cx = (g_mult[kx>>2] >> ((kx&3)*8)) & 0xFFu;
    unsigned cy = (g_mult[ky>>2] >> ((ky&3)*8)) & 0xFFu;
    int bx = ((int)b.x) << 14;
    int by = ((int)b.y) << 14;
    int px = atomicAdd(&g_curs[s.x], 1);
    g_sent[px] = d.x | bx;  g_w0[px] = 1.f/(float)cx;
    g_dent[atomicAdd(&g_curd[d.x], 1)] = s.x | bx;
    int py = atomicAdd(&g_curs[s.y], 1);
    g_sent[py] = d.y | by;  g_w0[py] = 1.f/(float)cy;
    g_dent[atomicAdd(&g_curd[d.y], 1)] = s.y | by;
}

// ---------------- k1: AH gather + ft0 = AH@M0 + b0 ----------------------------
__global__ void k1(const float* __restrict__ h){
    __shared__ float sM[DD*DD];
    __shared__ float srow[16][DD];
    int t = threadIdx.x;            // 256
    for (int x=t; x<DD*DD; x+=256) sM[x] = g_M[0][x];
    __syncthreads();
    int g  = t >> 4;
    int hl = t & 15;
    unsigned gmask = 0xFFFFu << (t & 16);
    int row = blockIdx.x*16 + g;
    int lo = g_offs[row], hi = g_offs[row+1];
    float4 acc = make_float4(0,0,0,0);
    #pragma unroll 4
    for (int i=lo; i<hi; i++){
        int w = g_sent[i];
        float w0 = g_w0[i];
        float4 v = ((const float4*)(h + (size_t)(w & 0x3FFF)*DD))[hl];
        acc.x += w0*v.x; acc.y += w0*v.y; acc.z += w0*v.z; acc.w += w0*v.w;
    }
    ((float4*)(g_AH + (size_t)row*DD))[hl] = acc;
    ((float4*)&srow[g][0])[hl] = acc;
    __syncwarp(gmask);
    float4 f  = ((const float4*)g_b[0])[hl];
    float4 f2 = make_float4(0,0,0,0);
    #pragma unroll 8
    for (int k=0;k<DD;k+=2){
        float a0 = srow[g][k];
        float a1 = srow[g][k+1];
        float4 w0v = ((const float4*)(sM + k*DD))[hl];
        float4 w1v = ((const float4*)(sM + (k+1)*DD))[hl];
        f.x  += a0*w0v.x; f.y  += a0*w0v.y; f.z  += a0*w0v.z; f.w  += a0*w0v.w;
        f2.x += a1*w1v.x; f2.y += a1*w1v.y; f2.z += a1*w1v.z; f2.w += a1*w1v.w;
    }
    f.x += f2.x; f.y += f2.y; f.z += f2.z; f.w += f2.w;
    ((float4*)(g_ft0 + (size_t)row*DD))[hl] = f;
}

// ---------------- k2: AH-gather w/ motif weights + ft1/ft2 --------------------
// ft_k[row] = (Σ w_k·AH[dst]) @ M_k + (Σ w_k)·b_k    (Z never materialized)
__global__ void k2(){
    __shared__ float sM1[DD*DD];
    __shared__ float sM2[DD*DD];
    __shared__ float srow[16][2*DD];
    int t = threadIdx.x;   // 256
    for (int x=t; x<DD*DD; x+=256){ sM1[x] = g_M[1][x]; sM2[x] = g_M[2][x]; }
    __syncthreads();
    int g  = t >> 4;
    int hl = t & 15;
    unsigned gmask = 0xFFFFu << (t & 16);
    int row = blockIdx.x*16 + g;
    int lo = g_offs[row], hi = g_offs[row+1];
    float4 acc1 = make_float4(0,0,0,0), acc2 = make_float4(0,0,0,0);
    float s1 = 0.f, s2 = 0.f;
    int o1 = 0, o2 = 0;
    #pragma unroll 4
    for (int i=lo; i<hi; i++){
        int w = g_sent[i];
        float w0 = g_w0[i];
        float w1 = (w & (1<<14)) ? w0 : 0.f;
        float w2 = (w & (1<<15)) ? w0 : 0.f;
        o1 |= (w >> 14) & 1;
        o2 |= (w >> 15) & 1;
        s1 += w1; s2 += w2;
        float4 v = ((const float4*)(g_AH + (size_t)(w & 0x3FFF)*DD))[hl];
        acc1.x += w1*v.x; acc1.y += w1*v.y; acc1.z += w1*v.z; acc1.w += w1*v.w;
        acc2.x += w2*v.x; acc2.y += w2*v.y; acc2.z += w2*v.z; acc2.w += w2*v.w;
    }
    if (hl == 0){ g_nm1[row] = o1; g_nm2[row] = o2; }
    ((float4*)&srow[g][0])[hl]  = acc1;
    ((float4*)&srow[g][DD])[hl] = acc2;
    __syncwarp(gmask);
    float4 b1 = ((const float4*)g_b[1])[hl];
    float4 b2 = ((const float4*)g_b[2])[hl];
    float4 f1  = make_float4(s1*b1.x, s1*b1.y, s1*b1.z, s1*b1.w);
    float4 f2  = make_float4(s2*b2.x, s2*b2.y, s2*b2.z, s2*b2.w);
    float4 f1b = make_float4(0,0,0,0), f2b = make_float4(0,0,0,0);
    #pragma unroll 8
    for (int k=0;k<DD;k+=2){
        float a1 = srow[g][k];
        float a2 = srow[g][DD+k];
        float c1 = srow[g][k+1];
        float c2 = srow[g][DD+k+1];
        float4 w1a = ((const float4*)(sM1 + k*DD))[hl];
        float4 w2a = ((const float4*)(sM2 + k*DD))[hl];
        float4 w1b = ((const float4*)(sM1 + (k+1)*DD))[hl];
        float4 w2b = ((const float4*)(sM2 + (k+1)*DD))[hl];
        f1.x  += a1*w1a.x; f1.y  += a1*w1a.y; f1.z  += a1*w1a.z; f1.w  += a1*w1a.w;
        f2.x  += a2*w2a.x; f2.y  += a2*w2a.y; f2.z  += a2*w2a.z; f2.w  += a2*w2a.w;
        f1b.x += c1*w1b.x; f1b.y += c1*w1b.y; f1b.z += c1*w1b.z; f1b.w += c1*w1b.w;
        f2b.x += c2*w2b.x; f2b.y += c2*w2b.y; f2b.z += c2*w2b.z; f2b.w += c2*w2b.w;
    }
    f1.x += f1b.x; f1.y += f1b.y; f1.z += f1b.z; f1.w += f1b.w;
    f2.x += f2b.x; f2.y += f2b.y; f2.z += f2b.z; f2.w += f2b.w;
    ((float4*)(g_ft1 + (size_t)row*DD))[hl] = f1;
    ((float4*)(g_ft2 + (size_t)row*DD))[hl] = f2;
}

// ---------------- fused attention (unroll-4 motif 0) --------------------------
#define ONLINE_UPD4(m, den, acc, p, v) do {              \
    float _mn = fmaxf((m), (p));                         \
    float _sc = __expf((m) - _mn);                       \
    float _w  = __expf((p) - _mn);                       \
    (den) = (den)*_sc + _w;                              \
    (acc).x = (acc).x*_sc + _w*(v).x;                    \
    (acc).y = (acc).y*_sc + _w*(v).y;                    \
    (acc).z = (acc).z*_sc + _w*(v).z;                    \
    (acc).w = (acc).w*_sc + _w*(v).w;                    \
    (m) = _mn;                                           \
} while(0)

#define ONLINE_UPD4X4(m, den, acc, pa, va, pb, vb, pc, vc, pd, vd) do { \
    float _mn = fmaxf(fmaxf((m), fmaxf((pa), (pb))), fmaxf((pc), (pd))); \
    float _sc = __expf((m) - _mn);                       \
    float _wa = __expf((pa) - _mn);                      \
    float _wb = __expf((pb) - _mn);                      \
    float _wc = __expf((pc) - _mn);                      \
    float _wd = __expf((pd) - _mn);                      \
    (den) = (den)*_sc + ((_wa + _wb) + (_wc + _wd));     \
    (acc).x = (acc).x*_sc + ((_wa*(va).x + _wb*(vb).x) + (_wc*(vc).x + _wd*(vd).x)); \
    (acc).y = (acc).y*_sc + ((_wa*(va).y + _wb*(vb).y) + (_wc*(vc).y + _wd*(vd).y)); \
    (acc).z = (acc).z*_sc + ((_wa*(va).z + _wb*(vb).z) + (_wc*(vc).z + _wd*(vd).z)); \
    (acc).w = (acc).w*_sc + ((_wa*(va).w + _wb*(vb).w) + (_wc*(vc).w + _wd*(vd).w)); \
    (m) = _mn;                                           \
} while(0)

__device__ __forceinline__ float red16(float p, unsigned gmask){
    #pragma unroll
    for (int o=8;o;o>>=1) p += __shfl_xor_sync(gmask, p, o);
    return p;
}
__device__ __forceinline__ float dot4(float4 a, float4 b){
    return a.x*b.x + a.y*b.y + a.z*b.z + a.w*b.w;
}

__global__ void k_attn(){
    __shared__ float sacc[3*DD];
    int t = threadIdx.x;
    for (int j=t; j<3*DD; j+=256) sacc[j] = 0.f;
    __syncthreads();
    int hl = t & 15;
    unsigned gmask = 0xFFFFu << (t & 16);
    int d  = (blockIdx.x*256 + t) >> 4;
    if (d < NN){
        int lo = g_offd[d], hi = g_offd[d+1];
        if (lo < hi){
            float4 f0 = ((const float4*)(g_ft0 + (size_t)d*DD))[hl];
            float4 f1 = ((const float4*)(g_ft1 + (size_t)d*DD))[hl];
            float4 f2 = ((const float4*)(g_ft2 + (size_t)d*DD))[hl];
            float m0=-FLT_MAX, den0=0.f; float4 a0 = make_float4(0,0,0,0);
            float m1=-FLT_MAX, den1=0.f; float4 a1 = make_float4(0,0,0,0);
            float m2=-FLT_MAX, den2=0.f; float4 a2 = make_float4(0,0,0,0);
            int i = lo;
            for (; i+3 < hi; i += 4){
                int wa = g_dent[i],   wb = g_dent[i+1];
                int wc = g_dent[i+2], wd = g_dent[i+3];
                int sa = wa & 0x3FFF, sb = wb & 0x3FFF;
                int sc = wc & 0x3FFF, sd = wd & 0x3FFF;
                if (hl == 0){
                    g_mult[((sa<<13)|d)>>2] = 0;  g_mult[((sb<<13)|d)>>2] = 0;
                    g_mult[((sc<<13)|d)>>2] = 0;  g_mult[((sd<<13)|d)>>2] = 0;
                }
                float4 va = ((const float4*)(g_ft0 + (size_t)sa*DD))[hl];
                float4 vb = ((const float4*)(g_ft0 + (size_t)sb*DD))[hl];
                float4 vc = ((const float4*)(g_ft0 + (size_t)sc*DD))[hl];
                float4 vd = ((const float4*)(g_ft0 + (size_t)sd*DD))[hl];
                float pa = red16(dot4(va, f0), gmask) * 0.125f;
                float pb = red16(dot4(vb, f0), gmask) * 0.125f;
                float pc = red16(dot4(vc, f0), gmask) * 0.125f;
                float pd = red16(dot4(vd, f0), gmask) * 0.125f;
                ONLINE_UPD4X4(m0, den0, a0, pa, va, pb, vb, pc, vc, pd, vd);
                int any12 = (wa | wb | wc | wd) & (3<<14);
                if (any12){
                    #pragma unroll
                    for (int u=0; u<4; u++){
                        int w = (u==0)?wa:((u==1)?wb:((u==2)?wc:wd));
                        int s = w & 0x3FFF;
                        if (w & (1<<14)){
                            float4 v1 = ((const float4*)(g_ft1 + (size_t)s*DD))[hl];
                            float p1 = red16(dot4(v1, f1), gmask) * 0.125f;
                            ONLINE_UPD4(m1, den1, a1, p1, v1);
                        }
                        if (w & (1<<15)){
                            float4 v2 = ((const float4*)(g_ft2 + (size_t)s*DD))[hl];
                            float p2 = red16(dot4(v2, f2), gmask) * 0.125f;
                            ONLINE_UPD4(m2, den2, a2, p2, v2);
                        }
                    }
                }
            }
            for (; i < hi; i++){
                int w = g_dent[i];
                int s = w & 0x3FFF;
                if (hl == 0) g_mult[((s<<13)|d)>>2] = 0;
                float4 v0 = ((const float4*)(g_ft0 + (size_t)s*DD))[hl];
                float p0 = red16(dot4(v0, f0), gmask) * 0.125f;
                ONLINE_UPD4(m0, den0, a0, p0, v0);
                if (w & (1<<14)){
                    float4 v1 = ((const float4*)(g_ft1 + (size_t)s*DD))[hl];
                    float p1 = red16(dot4(v1, f1), gmask) * 0.125f;
                    ONLINE_UPD4(m1, den1, a1, p1, v1);
                }
                if (w & (1<<15)){
                    float4 v2 = ((const float4*)(g_ft2 + (size_t)s*DD))[hl];
                    float p2 = red16(dot4(v2, f2), gmask) * 0.125f;
                    ONLINE_UPD4(m2, den2, a2, p2, v2);
                }
            }
            if (hl == 0){
                if (den1 > 0.f) g_nm1[d] = 1;
                if (den2 > 0.f) g_nm2[d] = 1;
            }
            float r0 = 1.f/fmaxf(den0, 1e-9f);
            atomicAdd(&sacc[4*hl+0], a0.x*r0); atomicAdd(&sacc[4*hl+1], a0.y*r0);
            atomicAdd(&sacc[4*hl+2], a0.z*r0); atomicAdd(&sacc[4*hl+3], a0.w*r0);
            if (den1 > 0.f){
                float r1 = 1.f/den1;
                atomicAdd(&sacc[DD+4*hl+0], a1.x*r1); atomicAdd(&sacc[DD+4*hl+1], a1.y*r1);
                atomicAdd(&sacc[DD+4*hl+2], a1.z*r1); atomicAdd(&sacc[DD+4*hl+3], a1.w*r1);
            }
            if (den2 > 0.f){
                float r2 = 1.f/den2;
                atomicAdd(&sacc[2*DD+4*hl+0], a2.x*r2); atomicAdd(&sacc[2*DD+4*hl+1], a2.y*r2);
                atomicAdd(&sacc[2*DD+4*hl+2], a2.z*r2); atomicAdd(&sacc[2*DD+4*hl+3], a2.w*r2);
            }
        }
    }
    __syncthreads();
    for (int j=t; j<3*DD; j+=256) atomicAdd(&g_pool[j], sacc[j]);
}

// ---------------- counts + final linear + pool clean ---------------------------
__global__ void k_nfinal(const float* __restrict__ lw, const float* __restrict__ lb,
                         float* __restrict__ out){
    __shared__ int sc1, sc2;
    __shared__ float s0[3*DD], s1[3*DD];
    int t = threadIdx.x;   // 256
    if (t == 0){ sc1 = 0; sc2 = 0; }
    __syncthreads();
    int c1 = 0, c2 = 0;
    for (int i=t; i<NN; i+=256){ c1 += g_nm1[i]; c2 += g_nm2[i]; }
    #pragma unroll
    for (int o=16;o;o>>=1){
        c1 += __shfl_xor_sync(0xffffffffu, c1, o);
        c2 += __shfl_xor_sync(0xffffffffu, c2, o);
    }
    if ((t & 31) == 0){ atomicAdd(&sc1, c1); atomicAdd(&sc2, c2); }
    __syncthreads();
    if (t < 3*DD){
        int k = t >> 6;
        float cnt = (k==0) ? (float)NN : fmaxf((float)(k==1 ? sc1 : sc2), 1.f);
        float p = g_pool[t] / cnt;
        g_pool[t] = 0.f;
        s0[t] = p * lw[t*2 + 0];
        s1[t] = p * lw[t*2 + 1];
    }
    __syncthreads();
    if (t == 0){
        float a = 0.f, b = 0.f;
        for (int i=0;i<3*DD;i++){ a += s0[i]; b += s1[i]; }
        out[0] = a + lb[0];
        out[1] = b + lb[1];
    }
}

// ---------------- host launcher -----------------------------------------------
extern "C" void kernel_launch(void* const* d_in, const int* in_sizes, int n_in,
                              void* d_out, int out_size){
    const float* h    = (const float*)d_in[0];
    const float* A1   = (const float*)d_in[2];
    const float* A2   = (const float*)d_in[3];
    const float* Ww   = (const float*)d_in[4];
    const float* Wb   = (const float*)d_in[5];
    const float* fc0  = (const float*)d_in[6];
    const float* fc1  = (const float*)d_in[7];
    const float* fc2  = (const float*)d_in[8];
    const float* linw = (const float*)d_in[9];
    const float* linb = (const float*)d_in[10];
    const int*   src  = (const int*)d_in[11];
    const int*   dst  = (const int*)d_in[12];
    float* out = (float*)d_out;

    k_histbits<<<512,  256>>>(src, dst, A1, A2);
    k_scan    <<<5,   1024>>>(Ww, Wb, fc0, fc1, fc2);
    k_scatter <<<1024, 256>>>(src, dst);
    k1        <<<512,  256>>>(h);
    k2        <<<512,  256>>>();
    k_attn    <<<512,  256>>>();
    k_nfinal  <<<1,    256>>>(linw, linb, out);
    (void)in_sizes; (void)n_in; (void)out_size;
}

// round 16
// speedup vs baseline: 1.1434x; 1.1434x over previous
#include <cuda_runtime.h>
#include <math.h>
#include <float.h>

#define NN 8192
#define DD 64
#define EE 524288

// ---------------- static device scratch -------------------------------------
__device__ __align__(16) float g_AH [NN*DD];
__device__ __align__(16) float g_ft0[NN*DD];
__device__ __align__(16) float g_ft1[NN*DD];
__device__ __align__(16) float g_ft2[NN*DD];
__device__ __align__(16) float g_w0 [EE];
__device__ __align__(16) int   g_sent[EE];     // dst | m1<<14 | m2<<15 (src-CSR)
__device__ __align__(16) int   g_dent[EE];     // src | m1<<14 | m2<<15 (dst-CSR)
__device__ __align__(16) unsigned char g_bits[EE];
__device__ __align__(16) unsigned g_mult[1<<24];  // 64MB byte-counters, key=(s<<13)|d
__device__ __align__(16) int   g_hists[NN];
__device__ __align__(16) int   g_histd[NN];
__device__ __align__(16) int   g_offs[NN+8];
__device__ __align__(16) int   g_offd[NN+8];
__device__ __align__(16) int   g_curs[NN];
__device__ __align__(16) int   g_curd[NN];
__device__ int   g_nm1[NN], g_nm2[NN];
__device__ float g_pool[3*DD];
__device__ __align__(16) float g_M [3][DD*DD]; // M_k = Ww.T @ fc_k
__device__ __align__(16) float g_b [3][DD];    // b_k = Wb @ fc_k

// ---------------- hist + A1/A2 probes + multiplicity count (fused) -----------
__global__ void k_histbits(const int* __restrict__ src, const int* __restrict__ dst,
                           const float* __restrict__ A1, const float* __restrict__ A2){
    int e4 = blockIdx.x*blockDim.x + threadIdx.x;
    if (e4 >= EE/4) return;
    int4 s = ((const int4*)src)[e4];
    int4 d = ((const int4*)dst)[e4];
    float a1x = __ldcs(&A1[(size_t)s.x*NN + d.x]);
    float a1y = __ldcs(&A1[(size_t)s.y*NN + d.y]);
    float a1z = __ldcs(&A1[(size_t)s.z*NN + d.z]);
    float a1w = __ldcs(&A1[(size_t)s.w*NN + d.w]);
    float a2x = __ldcs(&A2[(size_t)s.x*NN + d.x]);
    float a2y = __ldcs(&A2[(size_t)s.y*NN + d.y]);
    float a2z = __ldcs(&A2[(size_t)s.z*NN + d.z]);
    float a2w = __ldcs(&A2[(size_t)s.w*NN + d.w]);
    int kx = (s.x<<13)|d.x, ky = (s.y<<13)|d.y, kz = (s.z<<13)|d.z, kw = (s.w<<13)|d.w;
    atomicAdd(&g_mult[kx>>2], 1u<<((kx&3)*8));
    atomicAdd(&g_mult[ky>>2], 1u<<((ky&3)*8));
    atomicAdd(&g_mult[kz>>2], 1u<<((kz&3)*8));
    atomicAdd(&g_mult[kw>>2], 1u<<((kw&3)*8));
    atomicAdd(&g_hists[s.x], 1); atomicAdd(&g_hists[s.y], 1);
    atomicAdd(&g_hists[s.z], 1); atomicAdd(&g_hists[s.w], 1);
    atomicAdd(&g_histd[d.x], 1); atomicAdd(&g_histd[d.y], 1);
    atomicAdd(&g_histd[d.z], 1); atomicAdd(&g_histd[d.w], 1);
    uchar4 b;
    b.x = (unsigned char)(((a1x > 0.f) ? 1 : 0) | ((a2x > 0.f) ? 2 : 0));
    b.y = (unsigned char)(((a1y > 0.f) ? 1 : 0) | ((a2y > 0.f) ? 2 : 0));
    b.z = (unsigned char)(((a1z > 0.f) ? 1 : 0) | ((a2z > 0.f) ? 2 : 0));
    b.w = (unsigned char)(((a1w > 0.f) ? 1 : 0) | ((a2w > 0.f) ? 2 : 0));
    ((uchar4*)g_bits)[e4] = b;
}

// ---------------- scan (blocks 0,1) + M_k/b_k precompute (blocks 2..4) --------
__global__ void k_scan(const float* __restrict__ Ww, const float* __restrict__ Wb,
                       const float* __restrict__ fc0, const float* __restrict__ fc1,
                       const float* __restrict__ fc2){
    int t = threadIdx.x;         // 1024
    if (blockIdx.x >= 2){
        int q = blockIdx.x - 2;
        const float* fc = (q==0) ? fc0 : (q==1 ? fc1 : fc2);
        __shared__ float sWw[DD*DD], sfc[DD*DD];
        for (int x=t; x<DD*DD; x+=1024){ sWw[x] = Ww[x]; sfc[x] = fc[x]; }
        __syncthreads();
        for (int x=t; x<DD*DD; x+=1024){
            int k = x >> 6, j = x & 63;
            float acc = 0.f, acc2 = 0.f;
            #pragma unroll 8
            for (int r=0;r<DD;r+=2){
                acc  += sWw[r*DD+k]     * sfc[r*DD+j];
                acc2 += sWw[(r+1)*DD+k] * sfc[(r+1)*DD+j];
            }
            g_M[q][x] = acc + acc2;
        }
        if (t < DD){
            float acc = 0.f;
            for (int r=0;r<DD;r++) acc += Wb[r] * sfc[r*DD+t];
            g_b[q][t] = acc;
        }
        return;
    }
    int* hist = blockIdx.x ? g_histd : g_hists;
    int* off  = blockIdx.x ? g_offd  : g_offs;
    int* cur  = blockIdx.x ? g_curd  : g_curs;
    __shared__ int wsum[32];
    int lane = t & 31, wid = t >> 5;
    int4 a = ((const int4*)hist)[2*t];
    int4 b = ((const int4*)hist)[2*t+1];
    int l0=a.x, l1=l0+a.y, l2=l1+a.z, l3=l2+a.w;
    int l4=l3+b.x, l5=l4+b.y, l6=l5+b.z, l7=l6+b.w;
    int4 z4 = make_int4(0,0,0,0);
    ((int4*)hist)[2*t]   = z4;
    ((int4*)hist)[2*t+1] = z4;
    int tot = l7;
    int pre = tot;
    #pragma unroll
    for (int o=1;o<32;o<<=1){ int v=__shfl_up_sync(0xffffffffu, pre, o); if (lane>=o) pre += v; }
    int wex = pre - tot;
    if (lane == 31) wsum[wid] = pre;
    __syncthreads();
    if (wid == 0){
        int v = wsum[lane];
        int p = v;
        #pragma unroll
        for (int o=1;o<32;o<<=1){ int u=__shfl_up_sync(0xffffffffu, p, o); if (lane>=o) p += u; }
        wsum[lane] = p - v;
    }
    __syncthreads();
    int base = wsum[wid] + wex;
    int4 o0 = make_int4(base,    base+l0, base+l1, base+l2);
    int4 o1 = make_int4(base+l3, base+l4, base+l5, base+l6);
    ((int4*)off)[2*t]   = o0;  ((int4*)off)[2*t+1] = o1;
    ((int4*)cur)[2*t]   = o0;  ((int4*)cur)[2*t+1] = o1;
    if (t == 1023) off[NN] = base + l7;
}

// ---------------- scatter: CSR build + w0 = 1/mult ----------------------------
__global__ void k_scatter(const int* __restrict__ src, const int* __restrict__ dst){
    int e2 = blockIdx.x*blockDim.x + threadIdx.x;
    if (e2 >= EE/2) return;
    int2 s = ((const int2*)src)[e2];
    int2 d = ((const int2*)dst)[e2];
    uchar2 b = ((const uchar2*)g_bits)[e2];
    int kx = (s.x<<13)|d.x, ky = (s.y<<13)|d.y;
    unsigned cx = (g_mult[kx>>2] >> ((kx&3)*8)) & 0xFFu;
    unsigned cy = (g_mult[ky>>2] >> ((ky&3)*8)) & 0xFFu;
    int bx = ((int)b.x) << 14;
    int by = ((int)b.y) << 14;
    int px = atomicAdd(&g_curs[s.x], 1);
    g_sent[px] = d.x | bx;  g_w0[px] = 1.f/(float)cx;
    g_dent[atomicAdd(&g_curd[d.x], 1)] = s.x | bx;
    int py = atomicAdd(&g_curs[s.y], 1);
    g_sent[py] = d.y | by;  g_w0[py] = 1.f/(float)cy;
    g_dent[atomicAdd(&g_curd[d.y], 1)] = s.y | by;
}

// ---------------- k1: AH gather + ft0 = AH@M0 + b0 ----------------------------
__global__ void k1(const float* __restrict__ h){
    __shared__ float sM[DD*DD];
    __shared__ float srow[16][DD];
    int t = threadIdx.x;            // 256
    for (int x=t; x<DD*DD; x+=256) sM[x] = g_M[0][x];
    __syncthreads();
    int g  = t >> 4;
    int hl = t & 15;
    unsigned gmask = 0xFFFFu << (t & 16);
    int row = blockIdx.x*16 + g;
    int lo = g_offs[row], hi = g_offs[row+1];
    float4 acc = make_float4(0,0,0,0);
    #pragma unroll 4
    for (int i=lo; i<hi; i++){
        int w = g_sent[i];
        float w0 = g_w0[i];
        float4 v = ((const float4*)(h + (size_t)(w & 0x3FFF)*DD))[hl];
        acc.x += w0*v.x; acc.y += w0*v.y; acc.z += w0*v.z; acc.w += w0*v.w;
    }
    ((float4*)(g_AH + (size_t)row*DD))[hl] = acc;
    ((float4*)&srow[g][0])[hl] = acc;
    __syncwarp(gmask);
    float4 f  = ((const float4*)g_b[0])[hl];
    float4 f2 = make_float4(0,0,0,0);
    #pragma unroll 8
    for (int k=0;k<DD;k+=2){
        float a0 = srow[g][k];
        float a1 = srow[g][k+1];
        float4 w0v = ((const float4*)(sM + k*DD))[hl];
        float4 w1v = ((const float4*)(sM + (k+1)*DD))[hl];
        f.x  += a0*w0v.x; f.y  += a0*w0v.y; f.z  += a0*w0v.z; f.w  += a0*w0v.w;
        f2.x += a1*w1v.x; f2.y += a1*w1v.y; f2.z += a1*w1v.z; f2.w += a1*w1v.w;
    }
    f.x += f2.x; f.y += f2.y; f.z += f2.z; f.w += f2.w;
    ((float4*)(g_ft0 + (size_t)row*DD))[hl] = f;
}

// ---------------- k2: AH-gather w/ motif weights + ft1/ft2 --------------------
__global__ void k2(){
    __shared__ float sM1[DD*DD];
    __shared__ float sM2[DD*DD];
    __shared__ float srow[16][2*DD];
    int t = threadIdx.x;   // 256
    for (int x=t; x<DD*DD; x+=256){ sM1[x] = g_M[1][x]; sM2[x] = g_M[2][x]; }
    __syncthreads();
    int g  = t >> 4;
    int hl = t & 15;
    unsigned gmask = 0xFFFFu << (t & 16);
    int row = blockIdx.x*16 + g;
    int lo = g_offs[row], hi = g_offs[row+1];
    float4 acc1 = make_float4(0,0,0,0), acc2 = make_float4(0,0,0,0);
    float s1 = 0.f, s2 = 0.f;
    int o1 = 0, o2 = 0;
    #pragma unroll 4
    for (int i=lo; i<hi; i++){
        int w = g_sent[i];
        float w0 = g_w0[i];
        float w1 = (w & (1<<14)) ? w0 : 0.f;
        float w2 = (w & (1<<15)) ? w0 : 0.f;
        o1 |= (w >> 14) & 1;
        o2 |= (w >> 15) & 1;
        s1 += w1; s2 += w2;
        float4 v = ((const float4*)(g_AH + (size_t)(w & 0x3FFF)*DD))[hl];
        acc1.x += w1*v.x; acc1.y += w1*v.y; acc1.z += w1*v.z; acc1.w += w1*v.w;
        acc2.x += w2*v.x; acc2.y += w2*v.y; acc2.z += w2*v.z; acc2.w += w2*v.w;
    }
    if (hl == 0){ g_nm1[row] = o1; g_nm2[row] = o2; }
    ((float4*)&srow[g][0])[hl]  = acc1;
    ((float4*)&srow[g][DD])[hl] = acc2;
    __syncwarp(gmask);
    float4 b1 = ((const float4*)g_b[1])[hl];
    float4 b2 = ((const float4*)g_b[2])[hl];
    float4 f1  = make_float4(s1*b1.x, s1*b1.y, s1*b1.z, s1*b1.w);
    float4 f2  = make_float4(s2*b2.x, s2*b2.y, s2*b2.z, s2*b2.w);
    float4 f1b = make_float4(0,0,0,0), f2b = make_float4(0,0,0,0);
    #pragma unroll 8
    for (int k=0;k<DD;k+=2){
        float a1 = srow[g][k];
        float a2 = srow[g][DD+k];
        float c1 = srow[g][k+1];
        float c2 = srow[g][DD+k+1];
        float4 w1a = ((const float4*)(sM1 + k*DD))[hl];
        float4 w2a = ((const float4*)(sM2 + k*DD))[hl];
        float4 w1b = ((const float4*)(sM1 + (k+1)*DD))[hl];
        float4 w2b = ((const float4*)(sM2 + (k+1)*DD))[hl];
        f1.x  += a1*w1a.x; f1.y  += a1*w1a.y; f1.z  += a1*w1a.z; f1.w  += a1*w1a.w;
        f2.x  += a2*w2a.x; f2.y  += a2*w2a.y; f2.z  += a2*w2a.z; f2.w  += a2*w2a.w;
        f1b.x += c1*w1b.x; f1b.y += c1*w1b.y; f1b.z += c1*w1b.z; f1b.w += c1*w1b.w;
        f2b.x += c2*w2b.x; f2b.y += c2*w2b.y; f2b.z += c2*w2b.z; f2b.w += c2*w2b.w;
    }
    f1.x += f1b.x; f1.y += f1b.y; f1.z += f1b.z; f1.w += f1b.w;
    f2.x += f2b.x; f2.y += f2b.y; f2.z += f2b.z; f2.w += f2b.w;
    ((float4*)(g_ft1 + (size_t)row*DD))[hl] = f1;
    ((float4*)(g_ft2 + (size_t)row*DD))[hl] = f2;
}

// ---------------- fused attention (unroll-2, R13 form) ------------------------
#define ONLINE_UPD4(m, den, acc, p, v) do {              \
    float _mn = fmaxf((m), (p));                         \
    float _sc = __expf((m) - _mn);                       \
    float _w  = __expf((p) - _mn);                       \
    (den) = (den)*_sc + _w;                              \
    (acc).x = (acc).x*_sc + _w*(v).x;                    \
    (acc).y = (acc).y*_sc + _w*(v).y;                    \
    (acc).z = (acc).z*_sc + _w*(v).z;                    \
    (acc).w = (acc).w*_sc + _w*(v).w;                    \
    (m) = _mn;                                           \
} while(0)

#define ONLINE_UPD4X2(m, den, acc, pa, va, pb, vb) do {  \
    float _mn = fmaxf((m), fmaxf((pa), (pb)));           \
    float _sc = __expf((m) - _mn);                       \
    float _wa = __expf((pa) - _mn);                      \
    float _wb = __expf((pb) - _mn);                      \
    (den) = (den)*_sc + _wa + _wb;                       \
    (acc).x = (acc).x*_sc + _wa*(va).x + _wb*(vb).x;     \
    (acc).y = (acc).y*_sc + _wa*(va).y + _wb*(vb).y;     \
    (acc).z = (acc).z*_sc + _wa*(va).z + _wb*(vb).z;     \
    (acc).w = (acc).w*_sc + _wa*(va).w + _wb*(vb).w;     \
    (m) = _mn;                                           \
} while(0)

__device__ __forceinline__ float red16(float p, unsigned gmask){
    #pragma unroll
    for (int o=8;o;o>>=1) p += __shfl_xor_sync(gmask, p, o);
    return p;
}
__device__ __forceinline__ float dot4(float4 a, float4 b){
    return a.x*b.x + a.y*b.y + a.z*b.z + a.w*b.w;
}

__global__ void k_attn(){
    __shared__ float sacc[3*DD];
    int t = threadIdx.x;
    for (int j=t; j<3*DD; j+=256) sacc[j] = 0.f;
    __syncthreads();
    int hl = t & 15;
    unsigned gmask = 0xFFFFu << (t & 16);
    int d  = (blockIdx.x*256 + t) >> 4;
    if (d < NN){
        int lo = g_offd[d], hi = g_offd[d+1];
        if (lo < hi){
            float4 f0 = ((const float4*)(g_ft0 + (size_t)d*DD))[hl];
            float4 f1 = ((const float4*)(g_ft1 + (size_t)d*DD))[hl];
            float4 f2 = ((const float4*)(g_ft2 + (size_t)d*DD))[hl];
            float m0=-FLT_MAX, den0=0.f; float4 a0 = make_float4(0,0,0,0);
            float m1=-FLT_MAX, den1=0.f; float4 a1 = make_float4(0,0,0,0);
            float m2=-FLT_MAX, den2=0.f; float4 a2 = make_float4(0,0,0,0);
            int i = lo;
            for (; i+1 < hi; i += 2){
                int wa = g_dent[i];
                int wb = g_dent[i+1];
                int sa = wa & 0x3FFF, sb = wb & 0x3FFF;
                if (hl == 0){
                    g_mult[((sa<<13)|d)>>2] = 0;
                    g_mult[((sb<<13)|d)>>2] = 0;
                }
                float4 va = ((const float4*)(g_ft0 + (size_t)sa*DD))[hl];
                float4 vb = ((const float4*)(g_ft0 + (size_t)sb*DD))[hl];
                float pa = red16(dot4(va, f0), gmask) * 0.125f;
                float pb = red16(dot4(vb, f0), gmask) * 0.125f;
                ONLINE_UPD4X2(m0, den0, a0, pa, va, pb, vb);
                if (wa & (1<<14)){
                    float4 v1 = ((const float4*)(g_ft1 + (size_t)sa*DD))[hl];
                    float p1 = red16(dot4(v1, f1), gmask) * 0.125f;
                    ONLINE_UPD4(m1, den1, a1, p1, v1);
                }
                if (wb & (1<<14)){
                    float4 v1 = ((const float4*)(g_ft1 + (size_t)sb*DD))[hl];
                    float p1 = red16(dot4(v1, f1), gmask) * 0.125f;
                    ONLINE_UPD4(m1, den1, a1, p1, v1);
                }
                if (wa & (1<<15)){
                    float4 v2 = ((const float4*)(g_ft2 + (size_t)sa*DD))[hl];
                    float p2 = red16(dot4(v2, f2), gmask) * 0.125f;
                    ONLINE_UPD4(m2, den2, a2, p2, v2);
                }
                if (wb & (1<<15)){
                    float4 v2 = ((const float4*)(g_ft2 + (size_t)sb*DD))[hl];
                    float p2 = red16(dot4(v2, f2), gmask) * 0.125f;
                    ONLINE_UPD4(m2, den2, a2, p2, v2);
                }
            }
            if (i < hi){
                int w = g_dent[i];
                int s = w & 0x3FFF;
                if (hl == 0) g_mult[((s<<13)|d)>>2] = 0;
                float4 v0 = ((const float4*)(g_ft0 + (size_t)s*DD))[hl];
                float p0 = red16(dot4(v0, f0), gmask) * 0.125f;
                ONLINE_UPD4(m0, den0, a0, p0, v0);
                if (w & (1<<14)){
                    float4 v1 = ((const float4*)(g_ft1 + (size_t)s*DD))[hl];
                    float p1 = red16(dot4(v1, f1), gmask) * 0.125f;
                    ONLINE_UPD4(m1, den1, a1, p1, v1);
                }
                if (w & (1<<15)){
                    float4 v2 = ((const float4*)(g_ft2 + (size_t)s*DD))[hl];
                    float p2 = red16(dot4(v2, f2), gmask) * 0.125f;
                    ONLINE_UPD4(m2, den2, a2, p2, v2);
                }
            }
            if (hl == 0){
                if (den1 > 0.f) g_nm1[d] = 1;
                if (den2 > 0.f) g_nm2[d] = 1;
            }
            float r0 = 1.f/fmaxf(den0, 1e-9f);
            atomicAdd(&sacc[4*hl+0], a0.x*r0); atomicAdd(&sacc[4*hl+1], a0.y*r0);
            atomicAdd(&sacc[4*hl+2], a0.z*r0); atomicAdd(&sacc[4*hl+3], a0.w*r0);
            if (den1 > 0.f){
                float r1 = 1.f/den1;
                atomicAdd(&sacc[DD+4*hl+0], a1.x*r1); atomicAdd(&sacc[DD+4*hl+1], a1.y*r1);
                atomicAdd(&sacc[DD+4*hl+2], a1.z*r1); atomicAdd(&sacc[DD+4*hl+3], a1.w*r1);
            }
            if (den2 > 0.f){
                float r2 = 1.f/den2;
                atomicAdd(&sacc[2*DD+4*hl+0], a2.x*r2); atomicAdd(&sacc[2*DD+4*hl+1], a2.y*r2);
                atomicAdd(&sacc[2*DD+4*hl+2], a2.z*r2); atomicAdd(&sacc[2*DD+4*hl+3], a2.w*r2);
            }
        }
    }
    __syncthreads();
    for (int j=t; j<3*DD; j+=256) atomicAdd(&g_pool[j], sacc[j]);
}

// ---------------- counts + final linear + pool clean ---------------------------
__global__ void k_nfinal(const float* __restrict__ lw, const float* __restrict__ lb,
                         float* __restrict__ out){
    __shared__ int sc1, sc2;
    __shared__ float s0[3*DD], s1[3*DD];
    int t = threadIdx.x;   // 256
    if (t == 0){ sc1 = 0; sc2 = 0; }
    __syncthreads();
    int c1 = 0, c2 = 0;
    for (int i=t; i<NN; i+=256){ c1 += g_nm1[i]; c2 += g_nm2[i]; }
    #pragma unroll
    for (int o=16;o;o>>=1){
        c1 += __shfl_xor_sync(0xffffffffu, c1, o);
        c2 += __shfl_xor_sync(0xffffffffu, c2, o);
    }
    if ((t & 31) == 0){ atomicAdd(&sc1, c1); atomicAdd(&sc2, c2); }
    __syncthreads();
    if (t < 3*DD){
        int k = t >> 6;
        float cnt = (k==0) ? (float)NN : fmaxf((float)(k==1 ? sc1 : sc2), 1.f);
        float p = g_pool[t] / cnt;
        g_pool[t] = 0.f;
        s0[t] = p * lw[t*2 + 0];
        s1[t] = p * lw[t*2 + 1];
    }
    __syncthreads();
    if (t == 0){
        float a = 0.f, b = 0.f;
        for (int i=0;i<3*DD;i++){ a += s0[i]; b += s1[i]; }
        out[0] = a + lb[0];
        out[1] = b + lb[1];
    }
}

// ---------------- host launcher -----------------------------------------------
extern "C" void kernel_launch(void* const* d_in, const int* in_sizes, int n_in,
                              void* d_out, int out_size){
    const float* h    = (const float*)d_in[0];
    const float* A1   = (const float*)d_in[2];
    const float* A2   = (const float*)d_in[3];
    const float* Ww   = (const float*)d_in[4];
    const float* Wb   = (const float*)d_in[5];
    const float* fc0  = (const float*)d_in[6];
    const float* fc1  = (const float*)d_in[7];
    const float* fc2  = (const float*)d_in[8];
    const float* linw = (const float*)d_in[9];
    const float* linb = (const float*)d_in[10];
    const int*   src  = (const int*)d_in[11];
    const int*   dst  = (const int*)d_in[12];
    float* out = (float*)d_out;

    k_histbits<<<512,  256>>>(src, dst, A1, A2);
    k_scan    <<<5,   1024>>>(Ww, Wb, fc0, fc1, fc2);
    k_scatter <<<1024, 256>>>(src, dst);
    k1        <<<512,  256>>>(h);
    k2        <<<512,  256>>>();
    k_attn    <<<512,  256>>>();
    k_nfinal  <<<1,    256>>>(linw, linb, out);
    (void)in_sizes; (void)n_in; (void)out_size;
}